// round 1
// baseline (speedup 1.0000x reference)
#include <cuda_runtime.h>
#include <math.h>

namespace {
constexpr int Bb = 4096, Dd = 64, Cc = 16, Hh = 512, NB = 2, NS = 8;
constexpr int BM = 128, BN = 64, BK = 16, TM = 8, TN = 4;
}

// scratch (allocation-free: device globals)
__device__ float g_y[Bb * Dd];
__device__ float g_yacc[Bb * Dd];
__device__ float g_yin[Bb * Dd];
__device__ float g_h1[Bb * Hh];
__device__ float g_h2[Bb * Hh];
__device__ float g_g1[Bb * Hh];
__device__ float g_cb[NB * Bb * Hh];
__device__ float g_G3[NB * Bb * Hh];
__device__ float g_ld[Bb];
__device__ float g_lds[Bb];

struct EpiP {
    const float* bias;
    const float* cbias;
    const float* w1t;
    float t;
    float* y; float* yacc; float* yin;
    float cacc, cin, cl;
    int stage;
    const float* eps;
    float* ld; float* lds;
};

// MODE: 0=cbias(NN,+b1) 1=G3(NT,plain) 2=F1(NN,tanh+cbias+t*w1t)
//       3=F2(NN,tanh+b2) 4=F3(NN,RK4 state epi) 5=B2(NT,A=G3*(1-h2^2))
//       6=B1(NT,A=g1*(1-h1^2), eps-dot + logdet epi)
template <int MODE>
__global__ void __launch_bounds__(256) gemm_k(
    const float* __restrict__ A, const float* __restrict__ A2,
    const float* __restrict__ Bm, float* __restrict__ C,
    int K, int lda, int ldb, int ldc, EpiP p)
{
    constexpr bool BT  = (MODE == 1 || MODE == 5 || MODE == 6);
    constexpr bool ATR = (MODE == 5 || MODE == 6);
    __shared__ float As[BK][BM];
    __shared__ float Bs[BK][BN];

    const int tid = threadIdx.x;
    const int tx = tid & 15, ty = tid >> 4;
    const int m0 = blockIdx.x * BM, n0 = blockIdx.y * BN;

    float acc[TM][TN] = {};

    const int ar = tid >> 2;              // 0..63
    const int ac = (tid & 3) << 2;        // 0,4,8,12

    for (int k0 = 0; k0 < K; k0 += BK) {
        // A tile: 128x16, transposed into As[k][m]
        #pragma unroll
        for (int pp = 0; pp < 2; pp++) {
            const int row = ar + pp * 64;
            const float* src = A + (size_t)(m0 + row) * lda + k0 + ac;
            float4 v = *(const float4*)src;
            if (ATR) {
                float4 h = *(const float4*)(A2 + (size_t)(m0 + row) * lda + k0 + ac);
                v.x *= 1.f - h.x * h.x; v.y *= 1.f - h.y * h.y;
                v.z *= 1.f - h.z * h.z; v.w *= 1.f - h.w * h.w;
            }
            As[ac + 0][row] = v.x; As[ac + 1][row] = v.y;
            As[ac + 2][row] = v.z; As[ac + 3][row] = v.w;
        }
        // B tile
        if (!BT) {
            const int br = tid >> 4, bc = (tid & 15) << 2;
            float4 v = *(const float4*)(Bm + (size_t)(k0 + br) * ldb + n0 + bc);
            *(float4*)&Bs[br][bc] = v;
        } else {
            const int bn = tid >> 2, bk = (tid & 3) << 2;
            float4 v = *(const float4*)(Bm + (size_t)(n0 + bn) * ldb + k0 + bk);
            Bs[bk + 0][bn] = v.x; Bs[bk + 1][bn] = v.y;
            Bs[bk + 2][bn] = v.z; Bs[bk + 3][bn] = v.w;
        }
        __syncthreads();
        #pragma unroll
        for (int kk = 0; kk < BK; kk++) {
            float a[TM], b[TN];
            #pragma unroll
            for (int i = 0; i < TM; i++) a[i] = As[kk][ty * TM + i];
            #pragma unroll
            for (int j = 0; j < TN; j++) b[j] = Bs[kk][tx * TN + j];
            #pragma unroll
            for (int i = 0; i < TM; i++)
                #pragma unroll
                for (int j = 0; j < TN; j++)
                    acc[i][j] = fmaf(a[i], b[j], acc[i][j]);
        }
        __syncthreads();
    }

    if (MODE == 6) {
        // gy = acc; l[b] = sum_n gy[b,n]*eps[b,n]; logdet update
        __shared__ float red[BM][17];
        #pragma unroll
        for (int i = 0; i < TM; i++) {
            const int m = m0 + ty * TM + i;
            float s = 0.f;
            #pragma unroll
            for (int j = 0; j < TN; j++) {
                const int n = tx * TN + j;
                s += acc[i][j] * p.eps[(size_t)m * Dd + n];
            }
            red[ty * TM + i][tx] = s;
        }
        __syncthreads();
        if (tid < BM) {
            float s = 0.f;
            #pragma unroll
            for (int t2 = 0; t2 < 16; t2++) s += red[tid][t2];
            const int m = m0 + tid;
            const float v = (p.stage == 1 ? p.ld[m] : p.lds[m]) + p.cl * s;
            if (p.stage == 4) p.ld[m] = v; else p.lds[m] = v;
        }
        return;
    }

    #pragma unroll
    for (int i = 0; i < TM; i++) {
        const int m = m0 + ty * TM + i;
        #pragma unroll
        for (int j = 0; j < TN; j++) {
            const int n = n0 + tx * TN + j;
            const float v = acc[i][j];
            const size_t idx = (size_t)m * ldc + n;
            if (MODE == 0) {
                C[idx] = v + p.bias[n];
            } else if (MODE == 1 || MODE == 5) {
                C[idx] = v;
            } else if (MODE == 2) {
                C[idx] = tanhf(v + p.cbias[idx] + p.t * p.w1t[n]);
            } else if (MODE == 3) {
                C[idx] = tanhf(v + p.bias[n]);
            } else if (MODE == 4) {
                const float kv = v + p.bias[n];
                const float ya = (p.stage == 1 ? p.y[idx] : p.yacc[idx]) + p.cacc * kv;
                if (p.stage == 4) { p.y[idx] = ya; p.yin[idx] = ya; }
                else { p.yacc[idx] = ya; p.yin[idx] = p.y[idx] + p.cin * kv; }
            }
        }
    }
}

__global__ void init_k(const float* __restrict__ x, float* __restrict__ y,
                       float* __restrict__ yin, float* __restrict__ ld) {
    const int i = blockIdx.x * blockDim.x + threadIdx.x;
    if (i < Bb * Dd) { y[i] = x[i]; yin[i] = x[i]; }
    if (i < Bb) ld[i] = 0.f;
}

__global__ void out_k(const float* __restrict__ y, const float* __restrict__ ld,
                      float* __restrict__ out) {
    const int i = blockIdx.x * blockDim.x + threadIdx.x;
    if (i >= Bb * (Dd + 1)) return;
    const int m = i / (Dd + 1), c = i % (Dd + 1);
    out[i] = (c < Dd) ? y[(size_t)m * Dd + c] : ld[m];
}

extern "C" void kernel_launch(void* const* d_in, const int* in_sizes, int n_in,
                              void* d_out, int out_size) {
    const float* x    = (const float*)d_in[0];
    const float* cond = (const float*)d_in[1];
    const float* eps  = (const float*)d_in[2];
    const float* W1   = (const float*)d_in[3];
    const float* b1   = (const float*)d_in[4];
    const float* W2   = (const float*)d_in[5];
    const float* b2   = (const float*)d_in[6];
    const float* W3   = (const float*)d_in[7];
    const float* b3   = (const float*)d_in[8];
    float* out = (float*)d_out;

    void *py, *pyacc, *pyin, *ph1, *ph2, *pg1, *pcb, *pG3, *pld, *plds;
    cudaGetSymbolAddress(&py, g_y);
    cudaGetSymbolAddress(&pyacc, g_yacc);
    cudaGetSymbolAddress(&pyin, g_yin);
    cudaGetSymbolAddress(&ph1, g_h1);
    cudaGetSymbolAddress(&ph2, g_h2);
    cudaGetSymbolAddress(&pg1, g_g1);
    cudaGetSymbolAddress(&pcb, g_cb);
    cudaGetSymbolAddress(&pG3, g_G3);
    cudaGetSymbolAddress(&pld, g_ld);
    cudaGetSymbolAddress(&plds, g_lds);
    float* y    = (float*)py;
    float* yacc = (float*)pyacc;
    float* yin  = (float*)pyin;
    float* h1   = (float*)ph1;
    float* h2   = (float*)ph2;
    float* g1   = (float*)pg1;
    float* cb   = (float*)pcb;
    float* G3   = (float*)pG3;
    float* ld   = (float*)pld;
    float* lds  = (float*)plds;

    init_k<<<(Bb * Dd + 255) / 256, 256>>>(x, y, yin, ld);

    const dim3 gBig(Bb / BM, Hh / BN);  // 32 x 8
    const dim3 gSm(Bb / BM, 1);         // 32 x 1
    const float dt = 1.0f / NS;

    for (int ib = 0; ib < NB; ib++) {
        const float* W1b  = W1 + (size_t)ib * (Dd + Cc + 1) * Hh;
        const float* b1b  = b1 + (size_t)ib * Hh;
        const float* W2b  = W2 + (size_t)ib * Hh * Hh;
        const float* b2b  = b2 + (size_t)ib * Hh;
        const float* W3b  = W3 + (size_t)ib * Hh * Dd;
        const float* b3b  = b3 + (size_t)ib * Dd;
        const float* epsb = eps + (size_t)ib * Bb * Dd;
        float* cbb = cb + (size_t)ib * Bb * Hh;
        float* G3b = G3 + (size_t)ib * Bb * Hh;

        {   // cbias = cond @ W1[64:80] + b1
            EpiP p{}; p.bias = b1b;
            gemm_k<0><<<gBig, 256>>>(cond, nullptr, W1b + (size_t)Dd * Hh, cbb,
                                     Cc, Cc, Hh, Hh, p);
        }
        {   // G3 = eps @ W3^T
            EpiP p{};
            gemm_k<1><<<gBig, 256>>>(epsb, nullptr, W3b, G3b,
                                     Dd, Dd, Dd, Hh, p);
        }

        for (int is = 0; is < NS; is++) {
            const float tbase = is * dt;
            for (int st = 1; st <= 4; st++) {
                const float t = tbase + (st == 1 ? 0.f : (st == 4 ? dt : 0.5f * dt));
                const float cacc = (st == 1 || st == 4) ? dt / 6.f : dt / 3.f;
                const float cin  = (st == 3) ? dt : 0.5f * dt;

                {   // F1: h1 = tanh(yin@W1y + cbias + t*w1t)
                    EpiP p{}; p.cbias = cbb; p.w1t = W1b + (size_t)(Dd + Cc) * Hh; p.t = t;
                    gemm_k<2><<<gBig, 256>>>(yin, nullptr, W1b, h1, Dd, Dd, Hh, Hh, p);
                }
                {   // F2: h2 = tanh(h1@W2 + b2)
                    EpiP p{}; p.bias = b2b;
                    gemm_k<3><<<gBig, 256>>>(h1, nullptr, W2b, h2, Hh, Hh, Hh, Hh, p);
                }
                {   // F3: k = h2@W3 + b3 ; RK4 state epilogue
                    EpiP p{}; p.bias = b3b; p.y = y; p.yacc = yacc; p.yin = yin;
                    p.cacc = cacc; p.cin = cin; p.stage = st;
                    gemm_k<4><<<gSm, 256>>>(h2, nullptr, W3b, nullptr, Hh, Hh, Dd, Dd, p);
                }
                {   // B2: g1 = (G3*(1-h2^2)) @ W2^T
                    EpiP p{};
                    gemm_k<5><<<gBig, 256>>>(G3b, h2, W2b, g1, Hh, Hh, Hh, Hh, p);
                }
                {   // B1: gy = (g1*(1-h1^2)) @ W1y^T ; l = <gy,eps> ; logdet epi
                    EpiP p{}; p.eps = epsb; p.ld = ld; p.lds = lds; p.cl = cacc; p.stage = st;
                    gemm_k<6><<<gSm, 256>>>(g1, h1, W1b, nullptr, Hh, Hh, Hh, Dd, p);
                }
            }
        }
    }

    out_k<<<(Bb * (Dd + 1) + 255) / 256, 256>>>(y, ld, out);
}

// round 2
// speedup vs baseline: 1.2442x; 1.2442x over previous
#include <cuda_runtime.h>
#include <math.h>

namespace {
constexpr int Bb = 4096, Dd = 64, Cc = 16, Hh = 512, NB = 2, NS = 8;
}

// scratch (allocation-free: device globals)
__device__ float g_y[Bb * Dd];
__device__ float g_yacc[Bb * Dd];
__device__ float g_yin[Bb * Dd];
__device__ float g_h1[Bb * Hh];
__device__ float g_h2[Bb * Hh];
__device__ float g_cb[NB * Bb * Hh];
__device__ float g_G3[NB * Bb * Hh];
__device__ float g_E1[NB * Bb * Hh];
__device__ float g_ld[Bb];
__device__ float g_psum[8 * Bb];

struct P {
    const float* A;     // main A matrix
    const float* A2;    // mask source (h2) / F3's A
    const float* B;     // main B matrix
    const float* Bf3;   // W3 for fused F3 part
    float* C;
    const float* bias;
    const float* cbias;
    const float* w1t;
    const float* h1;
    const float* E1;
    const float* b3;
    float* y; float* yacc; float* yin;
    float* ld; float* psum;
    int lda, ldc, stage;
    float t, cacc, cin, foldcoef;
};

// 64x64 tile, 256 threads, TM=TN=4, double-buffered smem.
// NT: B stored [n][k] row-major (transpose into smem). MASK: A *= (1-A2^2).
template <bool NT, bool MASK, int BK>
__device__ __forceinline__ void gemm_core(
    const float* __restrict__ A, const float* __restrict__ A2,
    const float* __restrict__ Bm,
    int K, int lda, int ldb, int m0, int n0,
    float (&acc)[4][4], float* sA, float* sB)
{
    const int tid = threadIdx.x;
    const int ar = tid & 63, acq = tid >> 6;    // A: row, k-chunk group
    const int tx = tid & 15, ty = tid >> 4;
    constexpr int NQ = BK / 16;
    float4 ra[NQ], rb[NQ];

    auto ldTiles = [&](int k0) {
        #pragma unroll
        for (int q = 0; q < NQ; q++) {
            const int kc = (acq + q * 4) * 4;
            ra[q] = *(const float4*)(A + (size_t)(m0 + ar) * lda + k0 + kc);
            if (MASK) {
                float4 h = *(const float4*)(A2 + (size_t)(m0 + ar) * lda + k0 + kc);
                ra[q].x *= 1.f - h.x * h.x; ra[q].y *= 1.f - h.y * h.y;
                ra[q].z *= 1.f - h.z * h.z; ra[q].w *= 1.f - h.w * h.w;
            }
        }
        if (!NT) {
            #pragma unroll
            for (int q = 0; q < NQ; q++) {
                const int bk = (tid >> 4) + q * 16;
                rb[q] = *(const float4*)(Bm + (size_t)(k0 + bk) * ldb + n0 + ((tid & 15) << 2));
            }
        } else {
            #pragma unroll
            for (int q = 0; q < NQ; q++) {
                const int kc = (tid >> 6) * 4 + q * 16;
                rb[q] = *(const float4*)(Bm + (size_t)(n0 + (tid & 63)) * ldb + k0 + kc);
            }
        }
    };
    auto stTiles = [&](int buf) {
        float* a = sA + buf * BK * 64;
        #pragma unroll
        for (int q = 0; q < NQ; q++) {
            const int kc = (acq + q * 4) * 4;
            a[(kc + 0) * 64 + ar] = ra[q].x; a[(kc + 1) * 64 + ar] = ra[q].y;
            a[(kc + 2) * 64 + ar] = ra[q].z; a[(kc + 3) * 64 + ar] = ra[q].w;
        }
        float* b = sB + buf * BK * 64;
        if (!NT) {
            #pragma unroll
            for (int q = 0; q < NQ; q++)
                *(float4*)&b[((tid >> 4) + q * 16) * 64 + ((tid & 15) << 2)] = rb[q];
        } else {
            #pragma unroll
            for (int q = 0; q < NQ; q++) {
                const int kc = (tid >> 6) * 4 + q * 16;
                const int bn = tid & 63;
                b[(kc + 0) * 64 + bn] = rb[q].x; b[(kc + 1) * 64 + bn] = rb[q].y;
                b[(kc + 2) * 64 + bn] = rb[q].z; b[(kc + 3) * 64 + bn] = rb[q].w;
            }
        }
    };

    ldTiles(0);
    stTiles(0);
    __syncthreads();
    int buf = 0;
    for (int k0 = BK; k0 <= K; k0 += BK) {
        if (k0 < K) ldTiles(k0);
        const float* a = sA + buf * BK * 64;
        const float* b = sB + buf * BK * 64;
        #pragma unroll
        for (int kk = 0; kk < BK; kk++) {
            float4 av = *(const float4*)&a[kk * 64 + ty * 4];
            float4 bv = *(const float4*)&b[kk * 64 + tx * 4];
            const float aa[4] = {av.x, av.y, av.z, av.w};
            const float bb[4] = {bv.x, bv.y, bv.z, bv.w};
            #pragma unroll
            for (int i = 0; i < 4; i++)
                #pragma unroll
                for (int j = 0; j < 4; j++)
                    acc[i][j] = fmaf(aa[i], bb[j], acc[i][j]);
        }
        if (k0 < K) { buf ^= 1; stTiles(buf); __syncthreads(); }
    }
}

// MODE: 0=cbias (NN K16, +b1)   1=G3 (NT K64)   2=E1 (NN K64)
//       3=F1 (NN K64, tanh(v+cbias+t*w1t)) + fold rider block (by==8)
//       4=F2 (NN K512, tanh(v+b2))
//       5=FUSED: by<8 -> B2 (NT K512, A=G3*(1-h2^2), epi: dot with (1-h1^2)*E1 -> psum)
//                by==8 -> F3 (NN K512, A=h2, B=W3, RK4 state epilogue)
template <int MODE>
__global__ void __launch_bounds__(256) k_main(P p)
{
    __shared__ float sA[2 * 32 * 64];
    __shared__ float sB[2 * 32 * 64];
    const int tid = threadIdx.x;
    const int tx = tid & 15, ty = tid >> 4;
    const int m0 = blockIdx.x * 64;
    const int by = blockIdx.y;
    const int n0 = by * 64;
    float acc[4][4] = {};

    if (MODE == 3 && by == 8) {
        // fold previous stage's logdet partials into ld
        if (p.foldcoef != 0.f && tid < 64) {
            const int m = m0 + tid;
            float s = 0.f;
            #pragma unroll
            for (int c = 0; c < 8; c++) s += p.psum[c * Bb + m];
            p.ld[m] += p.foldcoef * s;
        }
        return;
    }

    if (MODE == 5 && by == 8) {
        // F3: k = h2 @ W3 + b3 ; RK4 state update
        gemm_core<false, false, 32>(p.A2, nullptr, p.Bf3, Hh, Hh, Dd, m0, 0, acc, sA, sB);
        #pragma unroll
        for (int i = 0; i < 4; i++) {
            const int m = m0 + ty * 4 + i;
            #pragma unroll
            for (int j = 0; j < 4; j++) {
                const int n = tx * 4 + j;
                const float kv = acc[i][j] + p.b3[n];
                const size_t idx = (size_t)m * Dd + n;
                const float ya = (p.stage == 1 ? p.y[idx] : p.yacc[idx]) + p.cacc * kv;
                if (p.stage == 4) { p.y[idx] = ya; p.yin[idx] = ya; }
                else { p.yacc[idx] = ya; p.yin[idx] = p.y[idx] + p.cin * kv; }
            }
        }
        return;
    }

    if (MODE == 5) {
        // B2: g1 = (G3*(1-h2^2)) @ W2^T ; epi: psum[by][m] = sum_n g1*(1-h1^2)*E1
        gemm_core<true, true, 32>(p.A, p.A2, p.B, Hh, Hh, Hh, m0, n0, acc, sA, sB);
        __syncthreads();
        float* red = sA;   // 64 x 17
        #pragma unroll
        for (int i = 0; i < 4; i++) {
            const int m = m0 + ty * 4 + i;
            const float4 h = *(const float4*)(p.h1 + (size_t)m * Hh + n0 + tx * 4);
            const float4 e = *(const float4*)(p.E1 + (size_t)m * Hh + n0 + tx * 4);
            const float s = acc[i][0] * (1.f - h.x * h.x) * e.x
                          + acc[i][1] * (1.f - h.y * h.y) * e.y
                          + acc[i][2] * (1.f - h.z * h.z) * e.z
                          + acc[i][3] * (1.f - h.w * h.w) * e.w;
            red[(ty * 4 + i) * 17 + tx] = s;
        }
        __syncthreads();
        if (tid < 64) {
            float s = 0.f;
            #pragma unroll
            for (int c = 0; c < 16; c++) s += red[tid * 17 + c];
            p.psum[by * Bb + m0 + tid] = s;
        }
        return;
    }

    // plain GEMM modes
    if (MODE == 0)      gemm_core<false, false, 16>(p.A, nullptr, p.B, Cc, Cc, Hh, m0, n0, acc, sA, sB);
    else if (MODE == 1) gemm_core<true,  false, 32>(p.A, nullptr, p.B, Dd, Dd, Dd, m0, n0, acc, sA, sB);
    else if (MODE == 2) gemm_core<false, false, 32>(p.A, nullptr, p.B, Dd, Dd, Hh, m0, n0, acc, sA, sB);
    else if (MODE == 3) gemm_core<false, false, 32>(p.A, nullptr, p.B, Dd, p.lda, Hh, m0, n0, acc, sA, sB);
    else if (MODE == 4) gemm_core<false, false, 32>(p.A, nullptr, p.B, Hh, Hh, Hh, m0, n0, acc, sA, sB);

    #pragma unroll
    for (int i = 0; i < 4; i++) {
        const int m = m0 + ty * 4 + i;
        const int n = n0 + tx * 4;
        float4 v = make_float4(acc[i][0], acc[i][1], acc[i][2], acc[i][3]);
        if (MODE == 0) {
            const float4 bi = *(const float4*)(p.bias + n);
            v.x += bi.x; v.y += bi.y; v.z += bi.z; v.w += bi.w;
        } else if (MODE == 3) {
            const float4 cb = *(const float4*)(p.cbias + (size_t)m * Hh + n);
            const float4 wt = *(const float4*)(p.w1t + n);
            v.x = tanhf(v.x + cb.x + p.t * wt.x);
            v.y = tanhf(v.y + cb.y + p.t * wt.y);
            v.z = tanhf(v.z + cb.z + p.t * wt.z);
            v.w = tanhf(v.w + cb.w + p.t * wt.w);
        } else if (MODE == 4) {
            const float4 bi = *(const float4*)(p.bias + n);
            v.x = tanhf(v.x + bi.x); v.y = tanhf(v.y + bi.y);
            v.z = tanhf(v.z + bi.z); v.w = tanhf(v.w + bi.w);
        }
        *(float4*)(p.C + (size_t)m * p.ldc + n) = v;
    }
}

__global__ void init_k(const float* __restrict__ x, float* __restrict__ y,
                       float* __restrict__ yin, float* __restrict__ ld) {
    const int i = blockIdx.x * blockDim.x + threadIdx.x;
    if (i < Bb * Dd) { y[i] = x[i]; yin[i] = x[i]; }
    if (i < Bb) ld[i] = 0.f;
}

__global__ void out_k(const float* __restrict__ y, const float* __restrict__ ld,
                      const float* __restrict__ psum, float coef,
                      float* __restrict__ out) {
    const int i = blockIdx.x * blockDim.x + threadIdx.x;
    if (i >= Bb * (Dd + 1)) return;
    const int m = i / (Dd + 1), c = i % (Dd + 1);
    if (c < Dd) {
        out[i] = y[(size_t)m * Dd + c];
    } else {
        float s = 0.f;
        #pragma unroll
        for (int c2 = 0; c2 < 8; c2++) s += psum[c2 * Bb + m];
        out[i] = ld[m] + coef * s;
    }
}

extern "C" void kernel_launch(void* const* d_in, const int* in_sizes, int n_in,
                              void* d_out, int out_size) {
    const float* x    = (const float*)d_in[0];
    const float* cond = (const float*)d_in[1];
    const float* eps  = (const float*)d_in[2];
    const float* W1   = (const float*)d_in[3];
    const float* b1   = (const float*)d_in[4];
    const float* W2   = (const float*)d_in[5];
    const float* b2   = (const float*)d_in[6];
    const float* W3   = (const float*)d_in[7];
    const float* b3   = (const float*)d_in[8];
    float* out = (float*)d_out;

    void *py, *pyacc, *pyin, *ph1, *ph2, *pcb, *pG3, *pE1, *pld, *pps;
    cudaGetSymbolAddress(&py, g_y);
    cudaGetSymbolAddress(&pyacc, g_yacc);
    cudaGetSymbolAddress(&pyin, g_yin);
    cudaGetSymbolAddress(&ph1, g_h1);
    cudaGetSymbolAddress(&ph2, g_h2);
    cudaGetSymbolAddress(&pcb, g_cb);
    cudaGetSymbolAddress(&pG3, g_G3);
    cudaGetSymbolAddress(&pE1, g_E1);
    cudaGetSymbolAddress(&pld, g_ld);
    cudaGetSymbolAddress(&pps, g_psum);
    float* y    = (float*)py;
    float* yacc = (float*)pyacc;
    float* yin  = (float*)pyin;
    float* h1   = (float*)ph1;
    float* h2   = (float*)ph2;
    float* cb   = (float*)pcb;
    float* G3   = (float*)pG3;
    float* E1   = (float*)pE1;
    float* ld   = (float*)pld;
    float* psum = (float*)pps;

    init_k<<<(Bb * Dd + 255) / 256, 256>>>(x, y, yin, ld);

    const dim3 g8(Bb / 64, Hh / 64);       // (64, 8)
    const dim3 g9(Bb / 64, Hh / 64 + 1);   // (64, 9)
    const float dt = 1.0f / NS;
    float prev_cl = 0.f;

    for (int ib = 0; ib < NB; ib++) {
        const float* W1b  = W1 + (size_t)ib * (Dd + Cc + 1) * Hh;
        const float* b1b  = b1 + (size_t)ib * Hh;
        const float* W2b  = W2 + (size_t)ib * Hh * Hh;
        const float* b2b  = b2 + (size_t)ib * Hh;
        const float* W3b  = W3 + (size_t)ib * Hh * Dd;
        const float* b3b  = b3 + (size_t)ib * Dd;
        const float* epsb = eps + (size_t)ib * Bb * Dd;
        float* cbb = cb + (size_t)ib * Bb * Hh;
        float* G3b = G3 + (size_t)ib * Bb * Hh;
        float* E1b = E1 + (size_t)ib * Bb * Hh;

        {   // cbias = cond @ W1[64:80] + b1
            P p{}; p.A = cond; p.B = W1b + (size_t)Dd * Hh; p.C = cbb;
            p.bias = b1b; p.ldc = Hh;
            k_main<0><<<g8, 256>>>(p);
        }
        {   // G3 = eps @ W3^T
            P p{}; p.A = epsb; p.B = W3b; p.C = G3b; p.ldc = Hh;
            k_main<1><<<g8, 256>>>(p);
        }
        {   // E1 = eps @ W1y
            P p{}; p.A = epsb; p.B = W1b; p.C = E1b; p.ldc = Hh;
            k_main<2><<<g8, 256>>>(p);
        }

        for (int is = 0; is < NS; is++) {
            const float tbase = is * dt;
            for (int st = 1; st <= 4; st++) {
                const float t = tbase + (st == 1 ? 0.f : (st == 4 ? dt : 0.5f * dt));
                const float cacc = (st == 1 || st == 4) ? dt / 6.f : dt / 3.f;
                const float cin  = (st == 3) ? dt : 0.5f * dt;

                {   // F1 (+ fold rider)
                    P p{}; p.A = yin; p.B = W1b; p.C = h1; p.lda = Dd; p.ldc = Hh;
                    p.cbias = cbb; p.w1t = W1b + (size_t)(Dd + Cc) * Hh; p.t = t;
                    p.foldcoef = prev_cl; p.ld = ld; p.psum = psum;
                    k_main<3><<<g9, 256>>>(p);
                }
                {   // F2
                    P p{}; p.A = h1; p.B = W2b; p.C = h2; p.bias = b2b; p.ldc = Hh;
                    k_main<4><<<g8, 256>>>(p);
                }
                {   // FUSED: B2+logdet-dot (by<8) and F3+RK4 (by==8)
                    P p{}; p.A = G3b; p.A2 = h2; p.B = W2b; p.Bf3 = W3b;
                    p.h1 = h1; p.E1 = E1b; p.b3 = b3b; p.psum = psum;
                    p.y = y; p.yacc = yacc; p.yin = yin;
                    p.stage = st; p.cacc = cacc; p.cin = cin;
                    k_main<5><<<g9, 256>>>(p);
                }
                prev_cl = cacc;
            }
        }
    }

    out_k<<<(Bb * (Dd + 1) + 255) / 256, 256>>>(y, ld, psum, prev_cl, out);
}

// round 3
// speedup vs baseline: 2.6591x; 2.1373x over previous
#include <cuda_runtime.h>
#include <cuda_bf16.h>
#include <math.h>
#include <stdint.h>

namespace {
constexpr int Bb = 4096, Dd = 64, Cc = 16, Hh = 512, NB = 2, NS = 8;
constexpr int BM = 128, BN = 64, BK = 32;
constexpr int SAS = 40;                       // smem row stride (halves): 80B, 16B-aligned, conflict-free
constexpr int SMEM_A = 2 * BM * SAS;          // halves, per plane (2 bufs)
constexpr int SMEM_B = 2 * BN * SAS;
constexpr int SMEM_BYTES = (2 * SMEM_A + 2 * SMEM_B) * 2 + BM * 2 * 4;
}

// ---------------- device scratch (no allocations) ----------------
__device__ __nv_bfloat16 g_h1h[Bb * Hh], g_h1l[Bb * Hh];
__device__ __nv_bfloat16 g_h2h[Bb * Hh], g_h2l[Bb * Hh];
__device__ __nv_bfloat16 g_yinh[Bb * Dd], g_yinl[Bb * Dd];
__device__ float g_y[Bb * Dd], g_yacc[Bb * Dd];
__device__ float g_cb[NB * Bb * Hh], g_G3[NB * Bb * Hh], g_E1[NB * Bb * Hh];
__device__ float g_ld[Bb], g_psum[8 * Bb];
// weight/eps planes (hi/lo bf16)
__device__ __nv_bfloat16 g_epsh[NB * Bb * Dd],  g_epsl[NB * Bb * Dd];
__device__ __nv_bfloat16 g_W2h [NB * Hh * Hh],  g_W2l [NB * Hh * Hh];   // as-is   [n][k] for B2
__device__ __nv_bfloat16 g_W2Th[NB * Hh * Hh],  g_W2Tl[NB * Hh * Hh];   // [n][k]=W2[k][n] for F2
__device__ __nv_bfloat16 g_W3h [NB * Hh * Dd],  g_W3l [NB * Hh * Dd];   // as-is   [512][64] for G3
__device__ __nv_bfloat16 g_W3Th[NB * Dd * Hh],  g_W3Tl[NB * Dd * Hh];   // [64][512] for F3
__device__ __nv_bfloat16 g_W1yTh[NB * Hh * Dd], g_W1yTl[NB * Hh * Dd];  // [512][64] for F1/E1

// ---------------- small helpers ----------------
__device__ __forceinline__ uint32_t sptr(const void* p) {
    return (uint32_t)__cvta_generic_to_shared(p);
}
__device__ __forceinline__ void ldm4(uint32_t a, uint32_t& r0, uint32_t& r1,
                                     uint32_t& r2, uint32_t& r3) {
    asm volatile("ldmatrix.sync.aligned.m8n8.x4.shared.b16 {%0,%1,%2,%3}, [%4];"
                 : "=r"(r0), "=r"(r1), "=r"(r2), "=r"(r3) : "r"(a));
}
__device__ __forceinline__ void mma_bf16(float* c, const uint32_t* a, uint32_t b0, uint32_t b1) {
    asm volatile("mma.sync.aligned.m16n8k16.row.col.f32.bf16.bf16.f32 "
                 "{%0,%1,%2,%3}, {%4,%5,%6,%7}, {%8,%9}, {%0,%1,%2,%3};"
                 : "+f"(c[0]), "+f"(c[1]), "+f"(c[2]), "+f"(c[3])
                 : "r"(a[0]), "r"(a[1]), "r"(a[2]), "r"(a[3]), "r"(b0), "r"(b1));
}
__device__ __forceinline__ unsigned pack_split2(float v0, float v1, unsigned& lo_out) {
    __nv_bfloat16 h0 = __float2bfloat16(v0), h1 = __float2bfloat16(v1);
    __nv_bfloat16 l0 = __float2bfloat16(v0 - __bfloat162float(h0));
    __nv_bfloat16 l1 = __float2bfloat16(v1 - __bfloat162float(h1));
    lo_out = (unsigned)__bfloat16_as_ushort(l0) | ((unsigned)__bfloat16_as_ushort(l1) << 16);
    return (unsigned)__bfloat16_as_ushort(h0) | ((unsigned)__bfloat16_as_ushort(h1) << 16);
}
__device__ __forceinline__ float bf2sum(unsigned hi, unsigned lo, int half) {
    unsigned short h = (unsigned short)(half ? (hi >> 16) : hi);
    unsigned short l = (unsigned short)(half ? (lo >> 16) : lo);
    return __bfloat162float(__ushort_as_bfloat16(h)) + __bfloat162float(__ushort_as_bfloat16(l));
}

struct P {
    const __nv_bfloat16 *Ah, *Al;          // presplit A planes
    const float* Amask;                    // G3 (fp32) for masked A
    const __nv_bfloat16 *Mh, *Ml;          // h2 planes for mask
    const __nv_bfloat16 *Bh, *Bl;          // B planes
    const __nv_bfloat16 *F3Ah, *F3Al;      // F3 rider A (h2 planes)
    const __nv_bfloat16 *F3Bh, *F3Bl;      // F3 rider B (W3T planes)
    float* C;                              // fp32 output (MODE 0)
    const float *cbias, *w1t, *bias, *b3, *E1;
    const __nv_bfloat16 *h1h, *h1l;
    __nv_bfloat16 *Oh, *Ol;                // output planes
    float *y, *yacc, *ld, *psum;
    int lda, ldb, K, stage;
    float t, cacc, cin, foldcoef;
};

// MODE: 0 = plain fp32 C (G3/E1)
//       1 = F1: tanh(acc + cbias + t*w1t) -> h1 planes ; by==8: fold rider
//       2 = F2: tanh(acc + b2) -> h2 planes
//       3 = fused: by<8: B2 (A = G3*(1-h2^2) split on load) + logdet-dot -> psum
//                  by==8: F3 (A = h2 planes, B = W3T) + RK4 state epilogue
template <int MODE>
__global__ void __launch_bounds__(256, 1) mma_k(P p) {
    extern __shared__ __align__(16) char dynsmem[];
    __nv_bfloat16* sAh = (__nv_bfloat16*)dynsmem;
    __nv_bfloat16* sAl = sAh + SMEM_A;
    __nv_bfloat16* sBh = sAl + SMEM_A;
    __nv_bfloat16* sBl = sBh + SMEM_B;
    float* red = (float*)(sBl + SMEM_B);

    const int tid = threadIdx.x, lane = tid & 31, wid = tid >> 5;
    const int wm = wid & 3, wn = wid >> 2;
    const int m0 = blockIdx.x * BM;
    const int by = blockIdx.y;

    if (MODE == 1 && by == 8) {  // fold rider
        if (p.foldcoef != 0.f && tid < BM) {
            const int m = m0 + tid;
            float s = 0.f;
            #pragma unroll
            for (int c = 0; c < 8; c++) s += p.psum[c * Bb + m];
            p.ld[m] += p.foldcoef * s;
        }
        return;
    }

    const bool isF3 = (MODE == 3 && by == 8);
    const bool maskA = (MODE == 3) && !isF3;
    const int n0 = isF3 ? 0 : by * BN;
    const __nv_bfloat16* Ah = isF3 ? p.F3Ah : p.Ah;
    const __nv_bfloat16* Al = isF3 ? p.F3Al : p.Al;
    const __nv_bfloat16* Bhp = isF3 ? p.F3Bh : p.Bh;
    const __nv_bfloat16* Blp = isF3 ? p.F3Bl : p.Bl;
    const int lda = isF3 ? Hh : p.lda;
    const int ldb = isF3 ? Hh : p.ldb;
    const int K   = isF3 ? Hh : p.K;

    // ---- gmem staging layout ----
    const int arow = tid >> 1;            // 0..127
    const int acb  = (tid & 1) * 2;       // chunk (8-half) base: 0 or 2
    const int bn_  = tid >> 2;            // 0..63
    const int bc_  = tid & 3;

    uint4 rAh[2], rAl[2], rBh, rBl;

    auto loadG = [&](int k0) {
        if (!maskA) {
            const __nv_bfloat16* a = Ah + (size_t)(m0 + arow) * lda + k0 + acb * 8;
            rAh[0] = *(const uint4*)a; rAh[1] = *(const uint4*)(a + 8);
            const __nv_bfloat16* al = Al + (size_t)(m0 + arow) * lda + k0 + acb * 8;
            rAl[0] = *(const uint4*)al; rAl[1] = *(const uint4*)(al + 8);
        } else {
            const size_t off = (size_t)(m0 + arow) * Hh + k0 + acb * 8;
            float gv[16];
            #pragma unroll
            for (int q = 0; q < 4; q++)
                *(float4*)(gv + q * 4) = *(const float4*)(p.Amask + off + q * 4);
            uint4 mh[2] = {*(const uint4*)(p.Mh + off), *(const uint4*)(p.Mh + off + 8)};
            uint4 ml[2] = {*(const uint4*)(p.Ml + off), *(const uint4*)(p.Ml + off + 8)};
            const __nv_bfloat16* mhp = (const __nv_bfloat16*)mh;
            const __nv_bfloat16* mlp = (const __nv_bfloat16*)ml;
            __nv_bfloat16 oh[16], ol[16];
            #pragma unroll
            for (int i = 0; i < 16; i++) {
                const float h = __bfloat162float(mhp[i]) + __bfloat162float(mlp[i]);
                const float v = gv[i] * (1.f - h * h);
                const __nv_bfloat16 hv = __float2bfloat16(v);
                oh[i] = hv;
                ol[i] = __float2bfloat16(v - __bfloat162float(hv));
            }
            rAh[0] = ((uint4*)oh)[0]; rAh[1] = ((uint4*)oh)[1];
            rAl[0] = ((uint4*)ol)[0]; rAl[1] = ((uint4*)ol)[1];
        }
        rBh = *(const uint4*)(Bhp + (size_t)(n0 + bn_) * ldb + k0 + bc_ * 8);
        rBl = *(const uint4*)(Blp + (size_t)(n0 + bn_) * ldb + k0 + bc_ * 8);
    };
    auto storeS = [&](int buf) {
        const int ao = buf * BM * SAS + arow * SAS + acb * 8;
        *(uint4*)&sAh[ao]     = rAh[0];
        *(uint4*)&sAh[ao + 8] = rAh[1];
        *(uint4*)&sAl[ao]     = rAl[0];
        *(uint4*)&sAl[ao + 8] = rAl[1];
        const int bo = buf * BN * SAS + bn_ * SAS + bc_ * 8;
        *(uint4*)&sBh[bo] = rBh;
        *(uint4*)&sBl[bo] = rBl;
    };

    // ---- fragment addressing ----
    const int l7 = lane & 7;
    const int aro = l7 + ((lane >> 3) & 1) * 8;
    const int aco = (lane >> 4) * 8;
    const int bro = l7 + (lane >> 4) * 8;
    const int bco = ((lane >> 3) & 1) * 8;

    float acc[2][4][4] = {};

    auto compute = [&](int buf) {
        const uint32_t bAh = sptr(sAh + buf * BM * SAS);
        const uint32_t bAl = sptr(sAl + buf * BM * SAS);
        const uint32_t bBh = sptr(sBh + buf * BN * SAS);
        const uint32_t bBl = sptr(sBl + buf * BN * SAS);
        #pragma unroll
        for (int kk = 0; kk < 2; kk++) {
            uint32_t ah[2][4], al[2][4], bh[2][4], bl[2][4];
            #pragma unroll
            for (int mt = 0; mt < 2; mt++) {
                const uint32_t off = ((wm * 32 + mt * 16 + aro) * SAS + kk * 16 + aco) * 2;
                ldm4(bAh + off, ah[mt][0], ah[mt][1], ah[mt][2], ah[mt][3]);
                ldm4(bAl + off, al[mt][0], al[mt][1], al[mt][2], al[mt][3]);
            }
            #pragma unroll
            for (int pn = 0; pn < 2; pn++) {
                const uint32_t off = ((wn * 32 + pn * 16 + bro) * SAS + kk * 16 + bco) * 2;
                ldm4(bBh + off, bh[pn][0], bh[pn][1], bh[pn][2], bh[pn][3]);
                ldm4(bBl + off, bl[pn][0], bl[pn][1], bl[pn][2], bl[pn][3]);
            }
            #pragma unroll
            for (int mt = 0; mt < 2; mt++)
                #pragma unroll
                for (int nt = 0; nt < 4; nt++) {
                    const uint32_t b0h = bh[nt >> 1][(nt & 1) * 2], b1h = bh[nt >> 1][(nt & 1) * 2 + 1];
                    const uint32_t b0l = bl[nt >> 1][(nt & 1) * 2], b1l = bl[nt >> 1][(nt & 1) * 2 + 1];
                    mma_bf16(acc[mt][nt], ah[mt], b0h, b1h);
                    mma_bf16(acc[mt][nt], ah[mt], b0l, b1l);
                    mma_bf16(acc[mt][nt], al[mt], b0h, b1h);
                }
        }
    };

    // ---- pipelined main loop ----
    loadG(0);
    storeS(0);
    __syncthreads();
    int buf = 0;
    for (int k0 = BK;; k0 += BK) {
        const bool last = (k0 >= K);
        if (!last) loadG(k0);
        compute(buf);
        if (last) break;
        buf ^= 1;
        storeS(buf);
        __syncthreads();
    }

    // ---- epilogues ----
    const int g = lane >> 2, tt = lane & 3;

    if (MODE == 3 && !isF3) {  // B2: logdet partial dot
        float s[4] = {0.f, 0.f, 0.f, 0.f};
        #pragma unroll
        for (int mt = 0; mt < 2; mt++)
            #pragma unroll
            for (int nt = 0; nt < 4; nt++) {
                const int c = n0 + wn * 32 + nt * 8 + tt * 2;
                #pragma unroll
                for (int hr = 0; hr < 2; hr++) {
                    const int r = m0 + wm * 32 + mt * 16 + g + hr * 8;
                    const size_t off = (size_t)r * Hh + c;
                    const unsigned hh = *(const unsigned*)&p.h1h[off];
                    const unsigned hl = *(const unsigned*)&p.h1l[off];
                    const float2 e = *(const float2*)&p.E1[off];
                    const float h0 = bf2sum(hh, hl, 0), h1v = bf2sum(hh, hl, 1);
                    s[mt * 2 + hr] += acc[mt][nt][hr * 2 + 0] * (1.f - h0 * h0) * e.x
                                    + acc[mt][nt][hr * 2 + 1] * (1.f - h1v * h1v) * e.y;
                }
            }
        #pragma unroll
        for (int i = 0; i < 4; i++) {
            s[i] += __shfl_xor_sync(0xffffffffu, s[i], 1);
            s[i] += __shfl_xor_sync(0xffffffffu, s[i], 2);
        }
        if (tt == 0) {
            #pragma unroll
            for (int mt = 0; mt < 2; mt++)
                #pragma unroll
                for (int hr = 0; hr < 2; hr++)
                    red[(wm * 32 + mt * 16 + g + hr * 8) * 2 + wn] = s[mt * 2 + hr];
        }
        __syncthreads();
        if (tid < BM)
            p.psum[(size_t)by * Bb + m0 + tid] = red[tid * 2] + red[tid * 2 + 1];
        return;
    }

    if (isF3) {  // F3 + RK4
        unsigned* yinhU = (unsigned*)p.Oh;
        unsigned* yinlU = (unsigned*)p.Ol;
        #pragma unroll
        for (int mt = 0; mt < 2; mt++)
            #pragma unroll
            for (int nt = 0; nt < 4; nt++) {
                const int c = wn * 32 + nt * 8 + tt * 2;
                const float2 b3v = *(const float2*)&p.b3[c];
                #pragma unroll
                for (int hr = 0; hr < 2; hr++) {
                    const int r = m0 + wm * 32 + mt * 16 + g + hr * 8;
                    const size_t idx = (size_t)r * Dd + c;
                    const float kv0 = acc[mt][nt][hr * 2 + 0] + b3v.x;
                    const float kv1 = acc[mt][nt][hr * 2 + 1] + b3v.y;
                    float2 base = (p.stage == 1) ? *(const float2*)&p.y[idx]
                                                 : *(const float2*)&p.yacc[idx];
                    const float ya0 = base.x + p.cacc * kv0;
                    const float ya1 = base.y + p.cacc * kv1;
                    float yi0, yi1;
                    if (p.stage == 4) {
                        *(float2*)&p.y[idx] = make_float2(ya0, ya1);
                        yi0 = ya0; yi1 = ya1;
                    } else {
                        *(float2*)&p.yacc[idx] = make_float2(ya0, ya1);
                        const float2 yv = *(const float2*)&p.y[idx];
                        yi0 = yv.x + p.cin * kv0;
                        yi1 = yv.y + p.cin * kv1;
                    }
                    unsigned lo, hi = pack_split2(yi0, yi1, lo);
                    yinhU[idx >> 1] = hi;
                    yinlU[idx >> 1] = lo;
                }
            }
        return;
    }

    // MODE 0/1/2
    #pragma unroll
    for (int mt = 0; mt < 2; mt++)
        #pragma unroll
        for (int nt = 0; nt < 4; nt++) {
            const int c = n0 + wn * 32 + nt * 8 + tt * 2;
            #pragma unroll
            for (int hr = 0; hr < 2; hr++) {
                const int r = m0 + wm * 32 + mt * 16 + g + hr * 8;
                float v0 = acc[mt][nt][hr * 2 + 0];
                float v1 = acc[mt][nt][hr * 2 + 1];
                if (MODE == 0) {
                    *(float2*)&p.C[(size_t)r * Hh + c] = make_float2(v0, v1);
                } else {
                    if (MODE == 1) {
                        const float2 cb = *(const float2*)&p.cbias[(size_t)r * Hh + c];
                        const float2 wt = *(const float2*)&p.w1t[c];
                        v0 = tanhf(v0 + cb.x + p.t * wt.x);
                        v1 = tanhf(v1 + cb.y + p.t * wt.y);
                    } else {
                        const float2 bi = *(const float2*)&p.bias[c];
                        v0 = tanhf(v0 + bi.x);
                        v1 = tanhf(v1 + bi.y);
                    }
                    unsigned lo, hi = pack_split2(v0, v1, lo);
                    ((unsigned*)p.Oh)[((size_t)r * Hh + c) >> 1] = hi;
                    ((unsigned*)p.Ol)[((size_t)r * Hh + c) >> 1] = lo;
                }
            }
        }
}

// ---------------- aux kernels ----------------
__global__ void split_k(const float* __restrict__ src, __nv_bfloat16* __restrict__ h,
                        __nv_bfloat16* __restrict__ l, int n) {
    const int i = blockIdx.x * 256 + threadIdx.x;
    if (i < n) {
        const float v = src[i];
        const __nv_bfloat16 hv = __float2bfloat16(v);
        h[i] = hv;
        l[i] = __float2bfloat16(v - __bfloat162float(hv));
    }
}
__global__ void tsplit_k(const float* __restrict__ src, __nv_bfloat16* __restrict__ h,
                         __nv_bfloat16* __restrict__ l, int R, int C) {
    const int i = blockIdx.x * 256 + threadIdx.x;
    if (i < R * C) {
        const int r = i / C, c = i % C;
        const float v = src[i];
        const __nv_bfloat16 hv = __float2bfloat16(v);
        h[(size_t)c * R + r] = hv;
        l[(size_t)c * R + r] = __float2bfloat16(v - __bfloat162float(hv));
    }
}
__global__ void cbias_k(const float* __restrict__ cond, const float* __restrict__ W1c,
                        const float* __restrict__ b1, float* __restrict__ cb) {
    const int m = blockIdx.x;
    const int n = threadIdx.x * 4;
    float4 acc = *(const float4*)(b1 + n);
    #pragma unroll
    for (int k = 0; k < Cc; k++) {
        const float c = cond[m * Cc + k];
        const float4 w = *(const float4*)(W1c + (size_t)k * Hh + n);
        acc.x = fmaf(c, w.x, acc.x); acc.y = fmaf(c, w.y, acc.y);
        acc.z = fmaf(c, w.z, acc.z); acc.w = fmaf(c, w.w, acc.w);
    }
    *(float4*)(cb + (size_t)m * Hh + n) = acc;
}
__global__ void init_k(const float* __restrict__ x, float* __restrict__ y,
                       __nv_bfloat16* __restrict__ yinh, __nv_bfloat16* __restrict__ yinl,
                       float* __restrict__ ld) {
    const int i = blockIdx.x * blockDim.x + threadIdx.x;
    if (i < Bb * Dd) {
        const float v = x[i];
        y[i] = v;
        const __nv_bfloat16 hv = __float2bfloat16(v);
        yinh[i] = hv;
        yinl[i] = __float2bfloat16(v - __bfloat162float(hv));
    }
    if (i < Bb) ld[i] = 0.f;
}
__global__ void out_k(const float* __restrict__ y, const float* __restrict__ ld,
                      const float* __restrict__ psum, float coef, float* __restrict__ out) {
    const int i = blockIdx.x * blockDim.x + threadIdx.x;
    if (i >= Bb * (Dd + 1)) return;
    const int m = i / (Dd + 1), c = i % (Dd + 1);
    if (c < Dd) {
        out[i] = y[(size_t)m * Dd + c];
    } else {
        float s = 0.f;
        #pragma unroll
        for (int c2 = 0; c2 < 8; c2++) s += psum[c2 * Bb + m];
        out[i] = ld[m] + coef * s;
    }
}

// ---------------- host ----------------
extern "C" void kernel_launch(void* const* d_in, const int* in_sizes, int n_in,
                              void* d_out, int out_size) {
    const float* x    = (const float*)d_in[0];
    const float* cond = (const float*)d_in[1];
    const float* eps  = (const float*)d_in[2];
    const float* W1   = (const float*)d_in[3];
    const float* b1   = (const float*)d_in[4];
    const float* W2   = (const float*)d_in[5];
    const float* b2   = (const float*)d_in[6];
    const float* W3   = (const float*)d_in[7];
    const float* b3   = (const float*)d_in[8];
    float* out = (float*)d_out;

    cudaFuncSetAttribute(mma_k<0>, cudaFuncAttributeMaxDynamicSharedMemorySize, SMEM_BYTES);
    cudaFuncSetAttribute(mma_k<1>, cudaFuncAttributeMaxDynamicSharedMemorySize, SMEM_BYTES);
    cudaFuncSetAttribute(mma_k<2>, cudaFuncAttributeMaxDynamicSharedMemorySize, SMEM_BYTES);
    cudaFuncSetAttribute(mma_k<3>, cudaFuncAttributeMaxDynamicSharedMemorySize, SMEM_BYTES);

    #define SYM(T, v, s) T* v; { void* _p; cudaGetSymbolAddress(&_p, s); v = (T*)_p; }
    SYM(float, y, g_y) SYM(float, yacc, g_yacc) SYM(float, cb, g_cb)
    SYM(float, G3, g_G3) SYM(float, E1, g_E1) SYM(float, ld, g_ld) SYM(float, psum, g_psum)
    SYM(__nv_bfloat16, h1h, g_h1h) SYM(__nv_bfloat16, h1l, g_h1l)
    SYM(__nv_bfloat16, h2h, g_h2h) SYM(__nv_bfloat16, h2l, g_h2l)
    SYM(__nv_bfloat16, yinh, g_yinh) SYM(__nv_bfloat16, yinl, g_yinl)
    SYM(__nv_bfloat16, epsh, g_epsh) SYM(__nv_bfloat16, epsl, g_epsl)
    SYM(__nv_bfloat16, W2h, g_W2h) SYM(__nv_bfloat16, W2l, g_W2l)
    SYM(__nv_bfloat16, W2Th, g_W2Th) SYM(__nv_bfloat16, W2Tl, g_W2Tl)
    SYM(__nv_bfloat16, W3h, g_W3h) SYM(__nv_bfloat16, W3l, g_W3l)
    SYM(__nv_bfloat16, W3Th, g_W3Th) SYM(__nv_bfloat16, W3Tl, g_W3Tl)
    SYM(__nv_bfloat16, W1yTh, g_W1yTh) SYM(__nv_bfloat16, W1yTl, g_W1yTl)
    #undef SYM

    init_k<<<(Bb * Dd + 255) / 256, 256>>>(x, y, yinh, yinl, ld);

    const dim3 g8(Bb / BM, Hh / BN);       // (32, 8)
    const dim3 g9(Bb / BM, Hh / BN + 1);   // (32, 9)
    const float dt = 1.0f / NS;
    float prev_cl = 0.f;

    for (int ib = 0; ib < NB; ib++) {
        const float* W1b  = W1 + (size_t)ib * (Dd + Cc + 1) * Hh;
        const float* b1b  = b1 + (size_t)ib * Hh;
        const float* W2b  = W2 + (size_t)ib * Hh * Hh;
        const float* b2b  = b2 + (size_t)ib * Hh;
        const float* W3b  = W3 + (size_t)ib * Hh * Dd;
        const float* b3b  = b3 + (size_t)ib * Dd;
        const float* epsb = eps + (size_t)ib * Bb * Dd;
        float* cbb = cb + (size_t)ib * Bb * Hh;
        float* G3b = G3 + (size_t)ib * Bb * Hh;
        float* E1b = E1 + (size_t)ib * Bb * Hh;
        #define PL(v) (v + (size_t)ib * 0)
        __nv_bfloat16 *eph = epsh + (size_t)ib * Bb * Dd, *epl = epsl + (size_t)ib * Bb * Dd;
        __nv_bfloat16 *w2h = W2h + (size_t)ib * Hh * Hh, *w2l = W2l + (size_t)ib * Hh * Hh;
        __nv_bfloat16 *w2th = W2Th + (size_t)ib * Hh * Hh, *w2tl = W2Tl + (size_t)ib * Hh * Hh;
        __nv_bfloat16 *w3h = W3h + (size_t)ib * Hh * Dd, *w3l = W3l + (size_t)ib * Hh * Dd;
        __nv_bfloat16 *w3th = W3Th + (size_t)ib * Dd * Hh, *w3tl = W3Tl + (size_t)ib * Dd * Hh;
        __nv_bfloat16 *w1yth = W1yTh + (size_t)ib * Hh * Dd, *w1ytl = W1yTl + (size_t)ib * Hh * Dd;

        // precompute: splits / transposed splits
        split_k<<<(Bb * Dd + 255) / 256, 256>>>(epsb, eph, epl, Bb * Dd);
        split_k<<<(Hh * Hh + 255) / 256, 256>>>(W2b, w2h, w2l, Hh * Hh);
        split_k<<<(Hh * Dd + 255) / 256, 256>>>(W3b, w3h, w3l, Hh * Dd);
        tsplit_k<<<(Hh * Hh + 255) / 256, 256>>>(W2b, w2th, w2tl, Hh, Hh);
        tsplit_k<<<(Hh * Dd + 255) / 256, 256>>>(W3b, w3th, w3tl, Hh, Dd);
        tsplit_k<<<(Dd * Hh + 255) / 256, 256>>>(W1b, w1yth, w1ytl, Dd, Hh);
        cbias_k<<<Bb, 128>>>(cond, W1b + (size_t)Dd * Hh, b1b, cbb);

        {   // G3 = eps @ W3^T   (B plane = W3 as-is, [512][64])
            P p{}; p.Ah = eph; p.Al = epl; p.Bh = w3h; p.Bl = w3l;
            p.C = G3b; p.lda = Dd; p.ldb = Dd; p.K = Dd;
            mma_k<0><<<g8, 256, SMEM_BYTES>>>(p);
        }
        {   // E1 = eps @ W1y    (B plane = W1yT, [512][64])
            P p{}; p.Ah = eph; p.Al = epl; p.Bh = w1yth; p.Bl = w1ytl;
            p.C = E1b; p.lda = Dd; p.ldb = Dd; p.K = Dd;
            mma_k<0><<<g8, 256, SMEM_BYTES>>>(p);
        }

        for (int is = 0; is < NS; is++) {
            const float tbase = is * dt;
            for (int st = 1; st <= 4; st++) {
                const float t = tbase + (st == 1 ? 0.f : (st == 4 ? dt : 0.5f * dt));
                const float cacc = (st == 1 || st == 4) ? dt / 6.f : dt / 3.f;
                const float cin  = (st == 3) ? dt : 0.5f * dt;

                {   // F1 + fold rider
                    P p{}; p.Ah = yinh; p.Al = yinl; p.Bh = w1yth; p.Bl = w1ytl;
                    p.lda = Dd; p.ldb = Dd; p.K = Dd;
                    p.cbias = cbb; p.w1t = W1b + (size_t)(Dd + Cc) * Hh; p.t = t;
                    p.Oh = h1h; p.Ol = h1l;
                    p.foldcoef = prev_cl; p.ld = ld; p.psum = psum;
                    mma_k<1><<<g9, 256, SMEM_BYTES>>>(p);
                }
                {   // F2
                    P p{}; p.Ah = h1h; p.Al = h1l; p.Bh = w2th; p.Bl = w2tl;
                    p.lda = Hh; p.ldb = Hh; p.K = Hh;
                    p.bias = b2b; p.Oh = h2h; p.Ol = h2l;
                    mma_k<2><<<g8, 256, SMEM_BYTES>>>(p);
                }
                {   // FUSED: B2 + logdet dot (by<8), F3 + RK4 (by==8)
                    P p{};
                    p.Amask = G3b; p.Mh = h2h; p.Ml = h2l;
                    p.Bh = w2h; p.Bl = w2l;             // W2 as-is = (W2^T)[k][n] rows
                    p.F3Ah = h2h; p.F3Al = h2l; p.F3Bh = w3th; p.F3Bl = w3tl;
                    p.lda = Hh; p.ldb = Hh; p.K = Hh;
                    p.h1h = h1h; p.h1l = h1l; p.E1 = E1b; p.psum = psum;
                    p.b3 = b3b; p.y = y; p.yacc = yacc; p.Oh = yinh; p.Ol = yinl;
                    p.stage = st; p.cacc = cacc; p.cin = cin;
                    mma_k<3><<<g9, 256, SMEM_BYTES>>>(p);
                }
                prev_cl = cacc;
            }
        }
    }

    out_k<<<(Bb * (Dd + 1) + 255) / 256, 256>>>(y, ld, psum, prev_cl, out);
}

// round 5
// speedup vs baseline: 3.1871x; 1.1985x over previous
#include <cuda_runtime.h>
#include <cuda_bf16.h>
#include <math.h>
#include <stdint.h>

namespace {
constexpr int Bb = 4096, Dd = 64, Cc = 16, Hh = 512, NB = 2, NS = 8;
constexpr int SAS = 40;                 // smem row stride in halves (80B)
constexpr int PLANE = 2 * 128 * SAS;    // halves per plane (2 buffers)
constexpr int SMEM_BYTES = 4 * PLANE * 2 + 128 * 4 * 4;   // 4 planes + red
}

// ---------------- device scratch ----------------
__device__ __align__(16) __nv_bfloat16 g_h1h[Bb * Hh], g_h1l[Bb * Hh];
__device__ __align__(16) __nv_bfloat16 g_h2h[Bb * Hh], g_h2l[Bb * Hh];
__device__ __align__(16) __nv_bfloat16 g_yinh[Bb * Dd], g_yinl[Bb * Dd];
__device__ __align__(16) float g_y[Bb * Dd], g_yacc[Bb * Dd];
__device__ __align__(16) float g_cb[NB * Bb * Hh], g_G3[NB * Bb * Hh], g_E1[NB * Bb * Hh];
__device__ __align__(16) float g_ld[Bb], g_psum[4 * Bb];
__device__ __align__(16) __nv_bfloat16 g_epsh[NB * Bb * Dd],  g_epsl[NB * Bb * Dd];
__device__ __align__(16) __nv_bfloat16 g_W2h [NB * Hh * Hh],  g_W2l [NB * Hh * Hh];   // [n][k] B2
__device__ __align__(16) __nv_bfloat16 g_W2Th[NB * Hh * Hh],  g_W2Tl[NB * Hh * Hh];   // [n][k] F2
__device__ __align__(16) __nv_bfloat16 g_W3h [NB * Hh * Dd],  g_W3l [NB * Hh * Dd];   // [512][64] G3
__device__ __align__(16) __nv_bfloat16 g_W3Th[NB * Dd * Hh],  g_W3Tl[NB * Dd * Hh];   // [64][512] F3
__device__ __align__(16) __nv_bfloat16 g_W1yTh[NB * Hh * Dd], g_W1yTl[NB * Hh * Dd];  // [512][64] F1/E1

// ---------------- helpers ----------------
__device__ __forceinline__ uint32_t sptr(const void* p) {
    return (uint32_t)__cvta_generic_to_shared(p);
}
__device__ __forceinline__ void ldm4(uint32_t a, uint32_t& r0, uint32_t& r1,
                                     uint32_t& r2, uint32_t& r3) {
    asm volatile("ldmatrix.sync.aligned.m8n8.x4.shared.b16 {%0,%1,%2,%3}, [%4];"
                 : "=r"(r0), "=r"(r1), "=r"(r2), "=r"(r3) : "r"(a));
}
__device__ __forceinline__ void mma_bf16(float* c, const uint32_t* a, uint32_t b0, uint32_t b1) {
    asm volatile("mma.sync.aligned.m16n8k16.row.col.f32.bf16.bf16.f32 "
                 "{%0,%1,%2,%3}, {%4,%5,%6,%7}, {%8,%9}, {%0,%1,%2,%3};"
                 : "+f"(c[0]), "+f"(c[1]), "+f"(c[2]), "+f"(c[3])
                 : "r"(a[0]), "r"(a[1]), "r"(a[2]), "r"(a[3]), "r"(b0), "r"(b1));
}
__device__ __forceinline__ void cp16(void* dst, const void* src) {
    asm volatile("cp.async.cg.shared.global [%0], [%1], 16;"
                 :: "r"(sptr(dst)), "l"(src));
}
#define CP_COMMIT() asm volatile("cp.async.commit_group;" ::: "memory")
#define CP_WAIT1()  asm volatile("cp.async.wait_group 1;" ::: "memory")
#define CP_WAIT0()  asm volatile("cp.async.wait_group 0;" ::: "memory")

__device__ __forceinline__ unsigned pack_split2(float v0, float v1, unsigned& lo_out) {
    __nv_bfloat16 h0 = __float2bfloat16(v0), h1 = __float2bfloat16(v1);
    __nv_bfloat16 l0 = __float2bfloat16(v0 - __bfloat162float(h0));
    __nv_bfloat16 l1 = __float2bfloat16(v1 - __bfloat162float(h1));
    lo_out = (unsigned)__bfloat16_as_ushort(l0) | ((unsigned)__bfloat16_as_ushort(l1) << 16);
    return (unsigned)__bfloat16_as_ushort(h0) | ((unsigned)__bfloat16_as_ushort(h1) << 16);
}
__device__ __forceinline__ float bf2sum(unsigned hi, unsigned lo, int half) {
    unsigned short h = (unsigned short)(half ? (hi >> 16) : hi);
    unsigned short l = (unsigned short)(half ? (lo >> 16) : lo);
    return __bfloat162float(__ushort_as_bfloat16(h)) + __bfloat162float(__ushort_as_bfloat16(l));
}
__device__ __forceinline__ float ftanh(float x) {
    const float cx = fminf(fmaxf(x, -15.f), 15.f);
    const float e = __expf(2.f * cx);
    return __fdividef(e - 1.f, e + 1.f);
}

struct P {
    const __nv_bfloat16 *Ah, *Al, *Bh, *Bl, *B2h, *B2l;
    const float *Amask;
    const __nv_bfloat16 *Mh, *Ml;
    const __nv_bfloat16 *F3Ah, *F3Al, *F3Bh, *F3Bl;
    float *C, *C2;
    const float *cbias, *w1t, *bias, *b3, *E1;
    const __nv_bfloat16 *h1h, *h1l;
    __nv_bfloat16 *Oh, *Ol;
    float *y, *yacc, *ld, *psum;
    int stage;
    float t, cacc, cin, foldcoef;
};

// MODE 0: by<4 G3 / by>=4 E1 (K=64, fp32 C)                 grid (32,8)
// MODE 1: by<4 F1 (K=64, tanh epi) / by==4 fold rider       grid (32,5)
// MODE 2: F2 (K=512, tanh epi)                              grid (32,4)
// MODE 3: by<4 B2 (K=512, masked A, logdet dot) / by==4 F3  grid (32,5)
template <int MODE>
__global__ void __launch_bounds__(512, 1) mma_k(P p) {
    extern __shared__ __align__(16) char dynsmem[];
    __nv_bfloat16* sAh = (__nv_bfloat16*)dynsmem;
    __nv_bfloat16* sAl = sAh + PLANE;
    __nv_bfloat16* sBh = sAl + PLANE;
    __nv_bfloat16* sBl = sBh + PLANE;
    float* red = (float*)(sBl + PLANE);

    const int tid = threadIdx.x, lane = tid & 31, wid = tid >> 5;
    const int wm = wid & 3, wn = wid >> 2;
    const int m0 = blockIdx.x * 128, by = blockIdx.y;

    if (MODE == 1 && by == 4) {   // fold rider
        if (p.foldcoef != 0.f && tid < 128) {
            const int m = m0 + tid;
            float s = 0.f;
            #pragma unroll
            for (int c = 0; c < 4; c++) s += p.psum[c * Bb + m];
            p.ld[m] += p.foldcoef * s;
        }
        return;
    }

    const bool isF3 = (MODE == 3 && by == 4);
    const bool maskA = (MODE == 3) && !isF3;

    const __nv_bfloat16 *Ah, *Al, *Bhp, *Blp;
    int lda, ldb, K, N, n0;
    float* C0 = nullptr;
    if (MODE == 0) {
        K = 64; lda = 64; ldb = 64; N = 128;
        Ah = p.Ah; Al = p.Al;
        if (by < 4) { Bhp = p.Bh; Blp = p.Bl; C0 = p.C; n0 = by * 128; }
        else        { Bhp = p.B2h; Blp = p.B2l; C0 = p.C2; n0 = (by - 4) * 128; }
    } else if (MODE == 1) {
        K = 64; lda = 64; ldb = 64; N = 128; n0 = by * 128;
        Ah = p.Ah; Al = p.Al; Bhp = p.Bh; Blp = p.Bl;
    } else if (MODE == 2) {
        K = 512; lda = 512; ldb = 512; N = 128; n0 = by * 128;
        Ah = p.Ah; Al = p.Al; Bhp = p.Bh; Blp = p.Bl;
    } else if (!isF3) {
        K = 512; lda = 512; ldb = 512; N = 128; n0 = by * 128;
        Ah = nullptr; Al = nullptr; Bhp = p.Bh; Blp = p.Bl;
    } else {
        K = 512; lda = 512; ldb = 512; N = 64; n0 = 0;
        Ah = p.F3Ah; Al = p.F3Al; Bhp = p.F3Bh; Blp = p.F3Bl;
    }
    const int NT = K / 32;
    const int btot = N * 8;   // B cp.async chunks over both planes

    auto issue = [&](int kt) {
        const int buf = kt & 1;
        const int k0 = kt * 32;
        if (!maskA) {
            #pragma unroll
            for (int c = tid; c < 1024; c += 512) {
                const int plane = c >> 9, cc = c & 511;
                const int row = cc >> 2, ku = cc & 3;
                const __nv_bfloat16* src = (plane ? Al : Ah) + (size_t)(m0 + row) * lda + k0 + ku * 8;
                __nv_bfloat16* dst = (plane ? sAl : sAh) + buf * (PLANE / 2) + row * SAS + ku * 8;
                cp16(dst, src);
            }
        } else {
            const int row = tid >> 2, ku = tid & 3;
            const size_t go = (size_t)(m0 + row) * 512 + k0 + ku * 8;
            float g[8];
            *(float4*)(g)     = *(const float4*)(p.Amask + go);
            *(float4*)(g + 4) = *(const float4*)(p.Amask + go + 4);
            const uint4 mh4 = *(const uint4*)(p.Mh + go);
            const uint4 ml4 = *(const uint4*)(p.Ml + go);
            const __nv_bfloat16* mh = (const __nv_bfloat16*)&mh4;
            const __nv_bfloat16* ml = (const __nv_bfloat16*)&ml4;
            __nv_bfloat16 oh[8], ol[8];
            #pragma unroll
            for (int i = 0; i < 8; i++) {
                const float h = __bfloat162float(mh[i]) + __bfloat162float(ml[i]);
                const float v = g[i] * (1.f - h * h);
                oh[i] = __float2bfloat16(v);
                ol[i] = __float2bfloat16(v - __bfloat162float(oh[i]));
            }
            const int so = buf * (PLANE / 2) + row * SAS + ku * 8;
            *(uint4*)&sAh[so] = *(const uint4*)oh;
            *(uint4*)&sAl[so] = *(const uint4*)ol;
        }
        for (int c = tid; c < btot; c += 512) {
            const int plane = (c >= btot / 2), cc = plane ? c - btot / 2 : c;
            const int row = cc >> 2, ku = cc & 3;
            const __nv_bfloat16* src = (plane ? Blp : Bhp) + (size_t)(n0 + row) * ldb + k0 + ku * 8;
            __nv_bfloat16* dst = (plane ? sBl : sBh) + buf * (PLANE / 2) + row * SAS + ku * 8;
            cp16(dst, src);
        }
        CP_COMMIT();
    };

    // fragment addressing
    const int l7 = lane & 7;
    const int aro = l7 + ((lane >> 3) & 1) * 8;
    const int aco = (lane >> 4) * 8;
    const int bro = l7 + (lane >> 4) * 8;
    const int bco = ((lane >> 3) & 1) * 8;
    const bool active = (!isF3) || (wn < 2);

    float acc[2][4][4] = {};

    auto compute = [&](int buf) {
        if (!active) return;
        const uint32_t bAh = sptr(sAh + buf * (PLANE / 2));
        const uint32_t bAl = sptr(sAl + buf * (PLANE / 2));
        const uint32_t bBh = sptr(sBh + buf * (PLANE / 2));
        const uint32_t bBl = sptr(sBl + buf * (PLANE / 2));
        #pragma unroll
        for (int kk = 0; kk < 2; kk++) {
            uint32_t ah[2][4], al[2][4], bh[2][4], bl[2][4];
            #pragma unroll
            for (int mt = 0; mt < 2; mt++) {
                const uint32_t off = ((wm * 32 + mt * 16 + aro) * SAS + kk * 16 + aco) * 2;
                ldm4(bAh + off, ah[mt][0], ah[mt][1], ah[mt][2], ah[mt][3]);
                ldm4(bAl + off, al[mt][0], al[mt][1], al[mt][2], al[mt][3]);
            }
            #pragma unroll
            for (int pn = 0; pn < 2; pn++) {
                const uint32_t off = ((wn * 32 + pn * 16 + bro) * SAS + kk * 16 + bco) * 2;
                ldm4(bBh + off, bh[pn][0], bh[pn][1], bh[pn][2], bh[pn][3]);
                ldm4(bBl + off, bl[pn][0], bl[pn][1], bl[pn][2], bl[pn][3]);
            }
            #pragma unroll
            for (int mt = 0; mt < 2; mt++)
                #pragma unroll
                for (int nt = 0; nt < 4; nt++) {
                    const uint32_t b0h = bh[nt >> 1][(nt & 1) * 2], b1h = bh[nt >> 1][(nt & 1) * 2 + 1];
                    const uint32_t b0l = bl[nt >> 1][(nt & 1) * 2], b1l = bl[nt >> 1][(nt & 1) * 2 + 1];
                    mma_bf16(acc[mt][nt], ah[mt], b0h, b1h);
                    mma_bf16(acc[mt][nt], ah[mt], b0l, b1l);
                    mma_bf16(acc[mt][nt], al[mt], b0h, b1h);
                }
        }
    };

    issue(0);
    for (int kt = 0; kt < NT; kt++) {
        if (kt + 1 < NT) { issue(kt + 1); CP_WAIT1(); } else { CP_WAIT0(); }
        __syncthreads();
        compute(kt & 1);
        __syncthreads();
    }

    // ---- epilogues ----
    const int g = lane >> 2, tt = lane & 3;

    if (MODE == 3 && !isF3) {   // B2 logdet dot
        float s[4] = {0.f, 0.f, 0.f, 0.f};
        #pragma unroll
        for (int mt = 0; mt < 2; mt++)
            #pragma unroll
            for (int nt = 0; nt < 4; nt++) {
                const int c = n0 + wn * 32 + nt * 8 + tt * 2;
                #pragma unroll
                for (int hr = 0; hr < 2; hr++) {
                    const int r = m0 + wm * 32 + mt * 16 + g + hr * 8;
                    const size_t off = (size_t)r * 512 + c;
                    const unsigned hh = *(const unsigned*)&p.h1h[off];
                    const unsigned hl = *(const unsigned*)&p.h1l[off];
                    const float2 e = *(const float2*)&p.E1[off];
                    const float h0 = bf2sum(hh, hl, 0), h1v = bf2sum(hh, hl, 1);
                    s[mt * 2 + hr] += acc[mt][nt][hr * 2 + 0] * (1.f - h0 * h0) * e.x
                                    + acc[mt][nt][hr * 2 + 1] * (1.f - h1v * h1v) * e.y;
                }
            }
        #pragma unroll
        for (int i = 0; i < 4; i++) {
            s[i] += __shfl_xor_sync(0xffffffffu, s[i], 1);
            s[i] += __shfl_xor_sync(0xffffffffu, s[i], 2);
        }
        if (tt == 0) {
            #pragma unroll
            for (int mt = 0; mt < 2; mt++)
                #pragma unroll
                for (int hr = 0; hr < 2; hr++)
                    red[(wm * 32 + mt * 16 + g + hr * 8) * 4 + wn] = s[mt * 2 + hr];
        }
        __syncthreads();
        if (tid < 128) {
            const float* r4 = red + tid * 4;
            p.psum[(size_t)by * Bb + m0 + tid] = (r4[0] + r4[1]) + (r4[2] + r4[3]);
        }
        return;
    }

    if (isF3) {   // F3 + RK4
        if (!active) return;
        unsigned* yinhU = (unsigned*)p.Oh;
        unsigned* yinlU = (unsigned*)p.Ol;
        #pragma unroll
        for (int mt = 0; mt < 2; mt++)
            #pragma unroll
            for (int nt = 0; nt < 4; nt++) {
                const int c = wn * 32 + nt * 8 + tt * 2;
                const float2 b3v = *(const float2*)&p.b3[c];
                #pragma unroll
                for (int hr = 0; hr < 2; hr++) {
                    const int r = m0 + wm * 32 + mt * 16 + g + hr * 8;
                    const size_t idx = (size_t)r * 64 + c;
                    const float kv0 = acc[mt][nt][hr * 2 + 0] + b3v.x;
                    const float kv1 = acc[mt][nt][hr * 2 + 1] + b3v.y;
                    const float2 base = (p.stage == 1) ? *(const float2*)&p.y[idx]
                                                       : *(const float2*)&p.yacc[idx];
                    const float ya0 = base.x + p.cacc * kv0;
                    const float ya1 = base.y + p.cacc * kv1;
                    float yi0, yi1;
                    if (p.stage == 4) {
                        *(float2*)&p.y[idx] = make_float2(ya0, ya1);
                        yi0 = ya0; yi1 = ya1;
                    } else {
                        *(float2*)&p.yacc[idx] = make_float2(ya0, ya1);
                        const float2 yv = *(const float2*)&p.y[idx];
                        yi0 = yv.x + p.cin * kv0;
                        yi1 = yv.y + p.cin * kv1;
                    }
                    unsigned lo, hi = pack_split2(yi0, yi1, lo);
                    yinhU[idx >> 1] = hi;
                    yinlU[idx >> 1] = lo;
                }
            }
        return;
    }

    // MODE 0/1/2 fragment epilogues
    #pragma unroll
    for (int mt = 0; mt < 2; mt++)
        #pragma unroll
        for (int nt = 0; nt < 4; nt++) {
            const int c = n0 + wn * 32 + nt * 8 + tt * 2;
            #pragma unroll
            for (int hr = 0; hr < 2; hr++) {
                const int r = m0 + wm * 32 + mt * 16 + g + hr * 8;
                float v0 = acc[mt][nt][hr * 2 + 0];
                float v1 = acc[mt][nt][hr * 2 + 1];
                const size_t off = (size_t)r * 512 + c;
                if (MODE == 0) {
                    *(float2*)&C0[off] = make_float2(v0, v1);
                } else {
                    if (MODE == 1) {
                        const float2 cb = *(const float2*)&p.cbias[off];
                        const float2 wt = *(const float2*)&p.w1t[c];
                        v0 = ftanh(v0 + cb.x + p.t * wt.x);
                        v1 = ftanh(v1 + cb.y + p.t * wt.y);
                    } else {
                        const float2 bi = *(const float2*)&p.bias[c];
                        v0 = ftanh(v0 + bi.x);
                        v1 = ftanh(v1 + bi.y);
                    }
                    unsigned lo, hi = pack_split2(v0, v1, lo);
                    ((unsigned*)p.Oh)[off >> 1] = hi;
                    ((unsigned*)p.Ol)[off >> 1] = lo;
                }
            }
        }
}

// ---------------- aux kernels ----------------
__global__ void split_k(const float* __restrict__ src, __nv_bfloat16* __restrict__ h,
                        __nv_bfloat16* __restrict__ l, int n) {
    const int i = blockIdx.x * 256 + threadIdx.x;
    if (i < n) {
        const float v = src[i];
        const __nv_bfloat16 hv = __float2bfloat16(v);
        h[i] = hv;
        l[i] = __float2bfloat16(v - __bfloat162float(hv));
    }
}
__global__ void tsplit_k(const float* __restrict__ src, __nv_bfloat16* __restrict__ h,
                         __nv_bfloat16* __restrict__ l, int R, int C) {
    const int i = blockIdx.x * 256 + threadIdx.x;
    if (i < R * C) {
        const int r = i / C, c = i % C;
        const float v = src[i];
        const __nv_bfloat16 hv = __float2bfloat16(v);
        h[(size_t)c * R + r] = hv;
        l[(size_t)c * R + r] = __float2bfloat16(v - __bfloat162float(hv));
    }
}
__global__ void cbias_k(const float* __restrict__ cond, const float* __restrict__ W1c,
                        const float* __restrict__ b1, float* __restrict__ cb) {
    const int m = blockIdx.x;
    const int n = threadIdx.x * 4;
    float4 acc = *(const float4*)(b1 + n);
    #pragma unroll
    for (int k = 0; k < Cc; k++) {
        const float c = cond[m * Cc + k];
        const float4 w = *(const float4*)(W1c + (size_t)k * Hh + n);
        acc.x = fmaf(c, w.x, acc.x); acc.y = fmaf(c, w.y, acc.y);
        acc.z = fmaf(c, w.z, acc.z); acc.w = fmaf(c, w.w, acc.w);
    }
    *(float4*)(cb + (size_t)m * Hh + n) = acc;
}
__global__ void init_k(const float* __restrict__ x, float* __restrict__ y,
                       __nv_bfloat16* __restrict__ yinh, __nv_bfloat16* __restrict__ yinl,
                       float* __restrict__ ld) {
    const int i = blockIdx.x * blockDim.x + threadIdx.x;
    if (i < Bb * Dd) {
        const float v = x[i];
        y[i] = v;
        const __nv_bfloat16 hv = __float2bfloat16(v);
        yinh[i] = hv;
        yinl[i] = __float2bfloat16(v - __bfloat162float(hv));
    }
    if (i < Bb) ld[i] = 0.f;
}
__global__ void out_k(const float* __restrict__ y, const float* __restrict__ ld,
                      const float* __restrict__ psum, float coef, float* __restrict__ out) {
    const int i = blockIdx.x * blockDim.x + threadIdx.x;
    if (i >= Bb * (Dd + 1)) return;
    const int m = i / (Dd + 1), c = i % (Dd + 1);
    if (c < Dd) {
        out[i] = y[(size_t)m * Dd + c];
    } else {
        float s = 0.f;
        #pragma unroll
        for (int c2 = 0; c2 < 4; c2++) s += psum[c2 * Bb + m];
        out[i] = ld[m] + coef * s;
    }
}

// ---------------- host ----------------
extern "C" void kernel_launch(void* const* d_in, const int* in_sizes, int n_in,
                              void* d_out, int out_size) {
    const float* x    = (const float*)d_in[0];
    const float* cond = (const float*)d_in[1];
    const float* eps  = (const float*)d_in[2];
    const float* W1   = (const float*)d_in[3];
    const float* b1   = (const float*)d_in[4];
    const float* W2   = (const float*)d_in[5];
    const float* b2   = (const float*)d_in[6];
    const float* W3   = (const float*)d_in[7];
    const float* b3   = (const float*)d_in[8];
    float* out = (float*)d_out;

    cudaFuncSetAttribute(mma_k<0>, cudaFuncAttributeMaxDynamicSharedMemorySize, SMEM_BYTES);
    cudaFuncSetAttribute(mma_k<1>, cudaFuncAttributeMaxDynamicSharedMemorySize, SMEM_BYTES);
    cudaFuncSetAttribute(mma_k<2>, cudaFuncAttributeMaxDynamicSharedMemorySize, SMEM_BYTES);
    cudaFuncSetAttribute(mma_k<3>, cudaFuncAttributeMaxDynamicSharedMemorySize, SMEM_BYTES);

    #define SYM(T, v, s) T* v; { void* _p; cudaGetSymbolAddress(&_p, s); v = (T*)_p; }
    SYM(float, y, g_y) SYM(float, yacc, g_yacc) SYM(float, cb, g_cb)
    SYM(float, G3, g_G3) SYM(float, E1, g_E1) SYM(float, ld, g_ld) SYM(float, psum, g_psum)
    SYM(__nv_bfloat16, h1h, g_h1h) SYM(__nv_bfloat16, h1l, g_h1l)
    SYM(__nv_bfloat16, h2h, g_h2h) SYM(__nv_bfloat16, h2l, g_h2l)
    SYM(__nv_bfloat16, yinh, g_yinh) SYM(__nv_bfloat16, yinl, g_yinl)
    SYM(__nv_bfloat16, epsh, g_epsh) SYM(__nv_bfloat16, epsl, g_epsl)
    SYM(__nv_bfloat16, W2h, g_W2h) SYM(__nv_bfloat16, W2l, g_W2l)
    SYM(__nv_bfloat16, W2Th, g_W2Th) SYM(__nv_bfloat16, W2Tl, g_W2Tl)
    SYM(__nv_bfloat16, W3h, g_W3h) SYM(__nv_bfloat16, W3l, g_W3l)
    SYM(__nv_bfloat16, W3Th, g_W3Th) SYM(__nv_bfloat16, W3Tl, g_W3Tl)
    SYM(__nv_bfloat16, W1yTh, g_W1yTh) SYM(__nv_bfloat16, W1yTl, g_W1yTl)
    #undef SYM

    init_k<<<(Bb * Dd + 255) / 256, 256>>>(x, y, yinh, yinl, ld);

    const float dt = 1.0f / NS;
    float prev_cl = 0.f;

    for (int ib = 0; ib < NB; ib++) {
        const float* W1b  = W1 + (size_t)ib * (Dd + Cc + 1) * Hh;
        const float* b1b  = b1 + (size_t)ib * Hh;
        const float* W2b  = W2 + (size_t)ib * Hh * Hh;
        const float* b2b  = b2 + (size_t)ib * Hh;
        const float* W3b  = W3 + (size_t)ib * Hh * Dd;
        const float* b3b  = b3 + (size_t)ib * Dd;
        const float* epsb = eps + (size_t)ib * Bb * Dd;
        float* cbb = cb + (size_t)ib * Bb * Hh;
        float* G3b = G3 + (size_t)ib * Bb * Hh;
        float* E1b = E1 + (size_t)ib * Bb * Hh;
        __nv_bfloat16 *eph = epsh + (size_t)ib * Bb * Dd, *epl = epsl + (size_t)ib * Bb * Dd;
        __nv_bfloat16 *w2h = W2h + (size_t)ib * Hh * Hh, *w2l = W2l + (size_t)ib * Hh * Hh;
        __nv_bfloat16 *w2th = W2Th + (size_t)ib * Hh * Hh, *w2tl = W2Tl + (size_t)ib * Hh * Hh;
        __nv_bfloat16 *w3h = W3h + (size_t)ib * Hh * Dd, *w3l = W3l + (size_t)ib * Hh * Dd;
        __nv_bfloat16 *w3th = W3Th + (size_t)ib * Dd * Hh, *w3tl = W3Tl + (size_t)ib * Dd * Hh;
        __nv_bfloat16 *w1yth = W1yTh + (size_t)ib * Hh * Dd, *w1ytl = W1yTl + (size_t)ib * Hh * Dd;

        split_k<<<(Bb * Dd + 255) / 256, 256>>>(epsb, eph, epl, Bb * Dd);
        split_k<<<(Hh * Hh + 255) / 256, 256>>>(W2b, w2h, w2l, Hh * Hh);
        split_k<<<(Hh * Dd + 255) / 256, 256>>>(W3b, w3h, w3l, Hh * Dd);
        tsplit_k<<<(Hh * Hh + 255) / 256, 256>>>(W2b, w2th, w2tl, Hh, Hh);
        tsplit_k<<<(Hh * Dd + 255) / 256, 256>>>(W3b, w3th, w3tl, Hh, Dd);
        tsplit_k<<<(Dd * Hh + 255) / 256, 256>>>(W1b, w1yth, w1ytl, Dd, Hh);
        cbias_k<<<Bb, 128>>>(cond, W1b + (size_t)Dd * Hh, b1b, cbb);

        {   // merged G3 (by<4) + E1 (by>=4)
            P p{}; p.Ah = eph; p.Al = epl;
            p.Bh = w3h; p.Bl = w3l; p.C = G3b;
            p.B2h = w1yth; p.B2l = w1ytl; p.C2 = E1b;
            mma_k<0><<<dim3(32, 8), 512, SMEM_BYTES>>>(p);
        }

        for (int is = 0; is < NS; is++) {
            const float tbase = is * dt;
            for (int st = 1; st <= 4; st++) {
                const float t = tbase + (st == 1 ? 0.f : (st == 4 ? dt : 0.5f * dt));
                const float cacc = (st == 1 || st == 4) ? dt / 6.f : dt / 3.f;
                const float cin  = (st == 3) ? dt : 0.5f * dt;

                {   // F1 + fold rider
                    P p{}; p.Ah = yinh; p.Al = yinl; p.Bh = w1yth; p.Bl = w1ytl;
                    p.cbias = cbb; p.w1t = W1b + (size_t)(Dd + Cc) * Hh; p.t = t;
                    p.Oh = h1h; p.Ol = h1l;
                    p.foldcoef = prev_cl; p.ld = ld; p.psum = psum;
                    mma_k<1><<<dim3(32, 5), 512, SMEM_BYTES>>>(p);
                }
                {   // F2
                    P p{}; p.Ah = h1h; p.Al = h1l; p.Bh = w2th; p.Bl = w2tl;
                    p.bias = b2b; p.Oh = h2h; p.Ol = h2l;
                    mma_k<2><<<dim3(32, 4), 512, SMEM_BYTES>>>(p);
                }
                {   // FUSED: B2 + logdet dot (by<4), F3 + RK4 (by==4)
                    P p{};
                    p.Amask = G3b; p.Mh = h2h; p.Ml = h2l;
                    p.Bh = w2h; p.Bl = w2l;
                    p.F3Ah = h2h; p.F3Al = h2l; p.F3Bh = w3th; p.F3Bl = w3tl;
                    p.h1h = h1h; p.h1l = h1l; p.E1 = E1b; p.psum = psum;
                    p.b3 = b3b; p.y = y; p.yacc = yacc; p.Oh = yinh; p.Ol = yinl;
                    p.stage = st; p.cacc = cacc; p.cin = cin;
                    mma_k<3><<<dim3(32, 5), 512, SMEM_BYTES>>>(p);
                }
                prev_cl = cacc;
            }
        }
    }

    out_k<<<(Bb * (Dd + 1) + 255) / 256, 256>>>(y, ld, psum, prev_cl, out);
}